// round 12
// baseline (speedup 1.0000x reference)
#include <cuda_runtime.h>
#include <cuda_fp16.h>
#include <cstdint>

// ============================================================================
// Problem constants
// ============================================================================
#define N_ROWS   65536
#define IN_DIM   256
#define OUT_DIM  256
#define NTYPES   8
#define BM       64                        // rows per block tile
#define BN       256                       // cols per block tile (full OUT)
#define MAXTILES (N_ROWS / BM + NTYPES)    // 1032
#define KC       64                        // K-chunk (floats)
#define NCHUNK   (IN_DIM / KC)             // 4
#define GTHREADS 256
#define HIST_BLOCKS 64
#define WCONV_BLOCKS 512

// SMEM layout (bytes):
//  [0]      s_idx[64]      256B
//  [256]    s_bias[256]    1KB
//  [1536]   2 stages x (Araw fp32 64x256B = 16384 | B fp16 SW128 256x128B = 32768)
//  [99840]  Afp16 SW128 64x128B = 8192
#define OFF_STAGE0  1536
#define A_RAW_BYTES 16384
#define B_BYTES     32768
#define STAGE_BYTES (A_RAW_BYTES + B_BYTES)          // 49152
#define OFF_AF16    (OFF_STAGE0 + 2 * STAGE_BYTES)   // 99840
#define SMEM_BYTES  (OFF_AF16 + 8192)                // 108032

// ============================================================================
// Device scratch
// ============================================================================
__device__ int g_counts[NTYPES];   // reset by last scatter block each replay
__device__ int g_cursor[NTYPES];   // reset by last scatter block each replay
__device__ int g_done;             // scatter completion counter (self-resetting)
__device__ int g_idx[MAXTILES * BM];
__device__ int g_meta[MAXTILES];   // per tile: type | (valid_count << 8), or -1
__device__ __align__(16) __half g_Wh[NTYPES * OUT_DIM * IN_DIM];

// ============================================================================
// Helpers
// ============================================================================
__device__ __forceinline__ uint32_t smem_u32(const void* p) {
    uint32_t a;
    asm("{ .reg .u64 t; cvta.to.shared.u64 t, %1; cvt.u32.u64 %0, t; }" : "=r"(a) : "l"(p));
    return a;
}

__device__ __forceinline__ uint32_t swz(uint32_t off) { return off ^ ((off >> 3) & 0x70); }

__device__ __forceinline__ void cpa16(uint32_t dst, const void* src) {
    asm volatile("cp.async.cg.shared.global [%0], [%1], 16;" :: "r"(dst), "l"(src));
}
__device__ __forceinline__ void cpa_commit() {
    asm volatile("cp.async.commit_group;");
}
template <int N> __device__ __forceinline__ void cpa_wait() {
    asm volatile("cp.async.wait_group %0;" :: "n"(N) : "memory");
}

__device__ __forceinline__ void ldsm4(uint32_t* r, uint32_t addr) {
    asm volatile("ldmatrix.sync.aligned.m8n8.x4.shared.b16 {%0,%1,%2,%3}, [%4];"
                 : "=r"(r[0]), "=r"(r[1]), "=r"(r[2]), "=r"(r[3]) : "r"(addr));
}

__device__ __forceinline__ void mma16816(float* c, const uint32_t* a, uint32_t b0, uint32_t b1) {
    asm volatile("mma.sync.aligned.m16n8k16.row.col.f32.f16.f16.f32 "
                 "{%0,%1,%2,%3}, {%4,%5,%6,%7}, {%8,%9}, {%0,%1,%2,%3};"
                 : "+f"(c[0]), "+f"(c[1]), "+f"(c[2]), "+f"(c[3])
                 : "r"(a[0]), "r"(a[1]), "r"(a[2]), "r"(a[3]), "r"(b0), "r"(b1));
}

__device__ __forceinline__ uint32_t h2_as_u32(__half2 h) {
    return *reinterpret_cast<uint32_t*>(&h);
}

__device__ __forceinline__ void stcs2(float* p, float2 v) {
    asm volatile("st.global.cs.v2.f32 [%0], {%1, %2};" :: "l"(p), "f"(v.x), "f"(v.y));
}

__device__ __forceinline__ uint2 cvt4(float4 v) {
    __half2 h01 = __floats2half2_rn(v.x, v.y);
    __half2 h23 = __floats2half2_rn(v.z, v.w);
    return make_uint2(h2_as_u32(h01), h2_as_u32(h23));
}

// ============================================================================
// k_prep1: [0,64) histogram | [64,576) W->fp16
// ============================================================================
__global__ void __launch_bounds__(256) k_prep1(const float* __restrict__ W,
                                               const int* __restrict__ types) {
    const int bid = blockIdx.x, tid = threadIdx.x;

    if (bid < HIST_BLOCKS) {
        __shared__ int c[NTYPES];
        if (tid < NTYPES) c[tid] = 0;
        __syncthreads();
        int i = bid * 256 + tid;                       // [0, 16384)
        int4 tv = *(const int4*)(types + i * 4);
        atomicAdd(&c[tv.x], 1);
        atomicAdd(&c[tv.y], 1);
        atomicAdd(&c[tv.z], 1);
        atomicAdd(&c[tv.w], 1);
        __syncthreads();
        if (tid < NTYPES) atomicAdd(&g_counts[tid], c[tid]);
        return;
    }
    // ---- W convert: fp32 -> fp16 ----
    int i4 = (bid - HIST_BLOCKS) * 256 + tid;          // [0, 131072)
    float4 v = *(const float4*)(W + (size_t)i4 * 4);
    *(uint2*)(g_Wh + (size_t)i4 * 4) = cvt4(v);
}

// ============================================================================
// k_scatter: local prefix from g_counts, scatter rows, block 0 writes g_meta,
// last-finishing block resets counters (all blocks provably past their reads).
// ============================================================================
__global__ void __launch_bounds__(256) k_scatter(const int* __restrict__ types) {
    __shared__ int c[NTYPES], base[NTYPES];
    __shared__ int padstart[NTYPES], cnt[NTYPES];
    const int tid = threadIdx.x, bid = blockIdx.x;

    if (tid < NTYPES) { c[tid] = 0; cnt[tid] = g_counts[tid]; }
    __syncthreads();
    if (tid == 0) {
        int off = 0;
        for (int t = 0; t < NTYPES; t++) {
            padstart[t] = off;
            off += ((cnt[t] + BM - 1) / BM) * BM;
        }
    }
    __syncthreads();

    int i = bid * 256 + tid;                           // [0, 16384)
    int4 tv = *(const int4*)(types + i * 4);
    int p0 = atomicAdd(&c[tv.x], 1);
    int p1 = atomicAdd(&c[tv.y], 1);
    int p2 = atomicAdd(&c[tv.z], 1);
    int p3 = atomicAdd(&c[tv.w], 1);
    __syncthreads();
    if (tid < NTYPES) base[tid] = atomicAdd(&g_cursor[tid], c[tid]);
    __syncthreads();
    g_idx[padstart[tv.x] + base[tv.x] + p0] = i * 4;
    g_idx[padstart[tv.y] + base[tv.y] + p1] = i * 4 + 1;
    g_idx[padstart[tv.z] + base[tv.z] + p2] = i * 4 + 2;
    g_idx[padstart[tv.w] + base[tv.w] + p3] = i * 4 + 3;

    // block 0: per-tile metadata (type + valid row count in tile)
    if (bid == 0) {
        for (int tile = tid; tile < MAXTILES; tile += 256) {
            int meta = -1;
            for (int t = 0; t < NTYPES; t++) {
                int ts = padstart[t] / BM;
                int tn = (cnt[t] + BM - 1) / BM;
                if (tile >= ts && tile < ts + tn) {
                    int v = cnt[t] - (tile - ts) * BM;
                    if (v > BM) v = BM;
                    meta = t | (v << 8);
                }
            }
            g_meta[tile] = meta;
        }
    }

    // last block to arrive resets the counters for the next graph replay
    __syncthreads();
    __threadfence();
    if (tid == 0) {
        if (atomicAdd(&g_done, 1) == gridDim.x - 1) {
            for (int t = 0; t < NTYPES; t++) { g_counts[t] = 0; g_cursor[t] = 0; }
            g_done = 0;
        }
    }
}

// ============================================================================
// Grouped GEMM: one CTA per row-tile. D[64,256] = gather(x) * Wh[t]^T + b[t]
// A: cp.async raw fp32 -> bulk convert -> Afp16 SW128 -> ldmatrix.
// B: cp.async fp16 SW128 -> ldmatrix. 8 warps in 2(M)x4(N); warp tile 32x64.
// 64 fp32 acc/thread; 2 CTAs/SM; 2-stage pipeline, KC=64 (4 chunks).
// ============================================================================
__global__ void __launch_bounds__(GTHREADS, 2)
typed_linear_gemm(const float* __restrict__ x, const float* __restrict__ b,
                  float* __restrict__ out) {
    extern __shared__ char smem[];
    const int tile = blockIdx.x;
    const int meta = g_meta[tile];
    if (meta < 0) return;
    const int t    = meta & 0xFF;
    const int vcnt = meta >> 8;

    const int tid  = threadIdx.x;
    const int wid  = tid >> 5;
    const int lane = tid & 31;
    const uint32_t sb = smem_u32(smem);

    int*   s_idx  = (int*)smem;
    float* s_bias = (float*)(smem + 256);

    if (tid < BM) s_idx[tid] = (tid < vcnt) ? g_idx[tile * BM + tid] : -1;
    s_bias[tid] = b[t * OUT_DIM + tid];
    __syncthreads();

    const __half* Wh_t = g_Wh + (size_t)t * OUT_DIM * IN_DIM;

    // Per chunk: Araw = 64 rows x 64 fp32 (1024 x 16B, 4/thread, pitch 256B),
    //            B    = 256 rows x 64 fp16 SW128 (2048 x 16B, 8/thread).
    auto issue_chunk = [&](int c) {
        const int kb = c * KC;
        const uint32_t stg = sb + OFF_STAGE0 + (uint32_t)(c & 1) * STAGE_BYTES;
        #pragma unroll
        for (int r = 0; r < 4; ++r) {
            int i16 = r * GTHREADS + tid;          // [0,1024)
            int m = i16 >> 4, k4 = i16 & 15;
            int g = s_idx[m];
            cpa16(stg + (uint32_t)(m * 256 + k4 * 16),
                  x + (size_t)(g < 0 ? 0 : g) * IN_DIM + kb + k4 * 4);
        }
        #pragma unroll
        for (int r = 0; r < 8; ++r) {
            int i16 = r * GTHREADS + tid;          // [0,2048)
            int n = i16 >> 3, k16 = i16 & 7;
            cpa16(stg + A_RAW_BYTES + swz((uint32_t)(n * 128 + k16 * 16)),
                  Wh_t + (size_t)n * IN_DIM + kb + k16 * 8);
        }
        cpa_commit();
    };

    // -------- warp/lane constants for ldmatrix (SW128) --------
    const int mgrp = wid >> 2;      // rows [32*mgrp, +32)
    const int nq   = wid & 3;       // cols [64*nq, +64)
    const int j = lane & 7, sub = lane >> 3;

    const uint32_t Af = sb + OFF_AF16;
    uint32_t a_base[2], a_xr[2];
    #pragma unroll
    for (int mt = 0; mt < 2; ++mt) {
        int row = mgrp * 32 + mt * 16 + j + (sub & 1) * 8;
        a_xr[mt]   = (uint32_t)((row & 7) * 16);
        a_base[mt] = (uint32_t)(row * 128) + (uint32_t)((sub >> 1) * 16);
    }
    uint32_t b_base[4], b_xr[4];
    #pragma unroll
    for (int nt = 0; nt < 4; ++nt) {
        int row = nq * 64 + nt * 16 + (sub >> 1) * 8 + j;
        b_xr[nt]   = (uint32_t)((row & 7) * 16);
        b_base[nt] = (uint32_t)(row * 128) + (uint32_t)((sub & 1) * 16);
    }

    float acc[2][8][4];   // [mt][n8][quad]
    #pragma unroll
    for (int mt = 0; mt < 2; ++mt)
        #pragma unroll
        for (int i = 0; i < 8; ++i)
            #pragma unroll
            for (int q = 0; q < 4; ++q) acc[mt][i][q] = 0.f;

    issue_chunk(0);

    #pragma unroll
    for (int c = 0; c < NCHUNK; ++c) {
        const uint32_t stg_off = OFF_STAGE0 + (uint32_t)(c & 1) * STAGE_BYTES;
        const uint32_t Bh = sb + stg_off + A_RAW_BYTES;

        cpa_wait<0>();            // chunk c's Araw + B arrived
        __syncthreads();          // all warps past compute(c-1): Afp16 + other stage free

        if (c + 1 < NCHUNK) issue_chunk(c + 1);   // into the freed stage

        // ---- bulk convert Araw(c) fp32 -> Afp16 (SW128) ----
        #pragma unroll
        for (int r = 0; r < 4; ++r) {
            int i4 = r * GTHREADS + tid;           // [0,1024)
            int m = i4 >> 4, k4 = i4 & 15;
            float4 v = *(const float4*)(smem + stg_off + m * 256 + k4 * 16);
            if (s_idx[m] < 0) v = make_float4(0.f, 0.f, 0.f, 0.f);
            *(uint2*)(smem + OFF_AF16 + swz((uint32_t)(m * 128 + k4 * 8))) = cvt4(v);
        }
        __syncthreads();          // Afp16 visible to all warps

        // ---- compute chunk c: 4 K16 steps ----
        #pragma unroll
        for (int ks = 0; ks < 4; ++ks) {
            const uint32_t kbyte = (uint32_t)(ks * 32);
            uint32_t ah[2][4], bhr[4][4];
            #pragma unroll
            for (int mt = 0; mt < 2; ++mt)
                ldsm4(ah[mt], Af + ((a_base[mt] + kbyte) ^ a_xr[mt]));
            #pragma unroll
            for (int nt = 0; nt < 4; ++nt)
                ldsm4(bhr[nt], Bh + ((b_base[nt] + kbyte) ^ b_xr[nt]));
            #pragma unroll
            for (int nt = 0; nt < 4; ++nt)
                #pragma unroll
                for (int mt = 0; mt < 2; ++mt) {
                    mma16816(acc[mt][2 * nt],     ah[mt], bhr[nt][0], bhr[nt][1]);
                    mma16816(acc[mt][2 * nt + 1], ah[mt], bhr[nt][2], bhr[nt][3]);
                }
        }
    }

    // ---- epilogue: bias + scatter-store (streaming) ----
    #pragma unroll
    for (int mt = 0; mt < 2; ++mt) {
        const int r0 = mgrp * 32 + mt * 16 + (lane >> 2);
        const int g0 = s_idx[r0];
        const int g1 = s_idx[r0 + 8];
        #pragma unroll
        for (int n8 = 0; n8 < 8; ++n8) {
            const int col = nq * 64 + n8 * 8 + (lane & 3) * 2;
            const float bv0 = s_bias[col], bv1 = s_bias[col + 1];
            if (g0 >= 0)
                stcs2(out + (size_t)g0 * OUT_DIM + col,
                      make_float2(acc[mt][n8][0] + bv0, acc[mt][n8][1] + bv1));
            if (g1 >= 0)
                stcs2(out + (size_t)g1 * OUT_DIM + col,
                      make_float2(acc[mt][n8][2] + bv0, acc[mt][n8][3] + bv1));
        }
    }
}

// ============================================================================
// Launch
// ============================================================================
extern "C" void kernel_launch(void* const* d_in, const int* in_sizes, int n_in,
                              void* d_out, int out_size) {
    const float* x     = (const float*)d_in[0];
    const int*   types = (const int*)d_in[1];
    const float* W     = (const float*)d_in[2];
    const float* b     = (const float*)d_in[3];
    float*       out   = (float*)d_out;

    cudaFuncSetAttribute(typed_linear_gemm, cudaFuncAttributeMaxDynamicSharedMemorySize,
                         SMEM_BYTES);

    k_prep1<<<HIST_BLOCKS + WCONV_BLOCKS, 256>>>(W, types);
    k_scatter<<<HIST_BLOCKS, 256>>>(types);
    typed_linear_gemm<<<MAXTILES, GTHREADS, SMEM_BYTES>>>(x, b, out);
}

// round 13
// speedup vs baseline: 1.1173x; 1.1173x over previous
#include <cuda_runtime.h>
#include <cuda_fp16.h>
#include <cstdint>

// ============================================================================
// Problem constants
// ============================================================================
#define N_ROWS   65536
#define IN_DIM   256
#define OUT_DIM  256
#define NTYPES   8
#define BM       128                       // rows per block tile
#define BN       128                       // cols per block tile (OUT split in 2)
#define MAXTILES (N_ROWS / BM + NTYPES)    // 520 row-tiles
#define KC       64                        // K-chunk
#define NCHUNK   (IN_DIM / KC)             // 4
#define GTHREADS 256
#define HIST_BLOCKS 64
#define WCONV_BLOCKS 512
#define XCONV_BLOCKS 4096

// SMEM layout (bytes):
//  [0]      s_idx[128]     512B
//  [512]    s_bias[128]    512B
//  [1024]   3 stages x (Ah 16K | Bh 16K) = 96K
#define OFF_STAGE0  1024
#define STAGE_BYTES 32768
#define SMEM_BYTES  99328

// ============================================================================
// Device scratch
// ============================================================================
__device__ int g_counts[NTYPES];   // reset by last scatter block each replay
__device__ int g_cursor[NTYPES];   // reset by last scatter block each replay
__device__ int g_done;             // scatter completion counter (self-resetting)
__device__ int g_idx[MAXTILES * BM];
__device__ int g_meta[MAXTILES];   // per tile: type | (valid_count << 8), or -1
__device__ __align__(16) __half g_Wh[NTYPES * OUT_DIM * IN_DIM];
__device__ __align__(16) __half g_xh[N_ROWS * IN_DIM];          // 32 MB fp16 x

// ============================================================================
// Helpers
// ============================================================================
__device__ __forceinline__ uint32_t smem_u32(const void* p) {
    uint32_t a;
    asm("{ .reg .u64 t; cvta.to.shared.u64 t, %1; cvt.u32.u64 %0, t; }" : "=r"(a) : "l"(p));
    return a;
}

__device__ __forceinline__ uint32_t swz(uint32_t off) { return off ^ ((off >> 3) & 0x70); }

__device__ __forceinline__ void cpa16(uint32_t dst, const void* src) {
    asm volatile("cp.async.cg.shared.global [%0], [%1], 16;" :: "r"(dst), "l"(src));
}
__device__ __forceinline__ void cpa_commit() {
    asm volatile("cp.async.commit_group;");
}
template <int N> __device__ __forceinline__ void cpa_wait() {
    asm volatile("cp.async.wait_group %0;" :: "n"(N) : "memory");
}

__device__ __forceinline__ void ldsm4(uint32_t* r, uint32_t addr) {
    asm volatile("ldmatrix.sync.aligned.m8n8.x4.shared.b16 {%0,%1,%2,%3}, [%4];"
                 : "=r"(r[0]), "=r"(r[1]), "=r"(r[2]), "=r"(r[3]) : "r"(addr));
}

__device__ __forceinline__ void mma16816(float* c, const uint32_t* a, uint32_t b0, uint32_t b1) {
    asm volatile("mma.sync.aligned.m16n8k16.row.col.f32.f16.f16.f32 "
                 "{%0,%1,%2,%3}, {%4,%5,%6,%7}, {%8,%9}, {%0,%1,%2,%3};"
                 : "+f"(c[0]), "+f"(c[1]), "+f"(c[2]), "+f"(c[3])
                 : "r"(a[0]), "r"(a[1]), "r"(a[2]), "r"(a[3]), "r"(b0), "r"(b1));
}

__device__ __forceinline__ uint32_t h2_as_u32(__half2 h) {
    return *reinterpret_cast<uint32_t*>(&h);
}

__device__ __forceinline__ void stcs2(float* p, float2 v) {
    asm volatile("st.global.cs.v2.f32 [%0], {%1, %2};" :: "l"(p), "f"(v.x), "f"(v.y));
}

__device__ __forceinline__ uint2 cvt4(float4 v) {
    __half2 h01 = __floats2half2_rn(v.x, v.y);
    __half2 h23 = __floats2half2_rn(v.z, v.w);
    return make_uint2(h2_as_u32(h01), h2_as_u32(h23));
}

// ============================================================================
// k_prep1: [0,64) histogram | [64,576) W->fp16 | [576,4672) x->fp16
// ============================================================================
__global__ void __launch_bounds__(256) k_prep1(const float* __restrict__ W,
                                               const float* __restrict__ x,
                                               const int* __restrict__ types) {
    const int bid = blockIdx.x, tid = threadIdx.x;

    if (bid < HIST_BLOCKS) {
        __shared__ int c[NTYPES];
        if (tid < NTYPES) c[tid] = 0;
        __syncthreads();
        int i = bid * 256 + tid;                       // [0, 16384)
        int4 tv = *(const int4*)(types + i * 4);
        atomicAdd(&c[tv.x], 1);
        atomicAdd(&c[tv.y], 1);
        atomicAdd(&c[tv.z], 1);
        atomicAdd(&c[tv.w], 1);
        __syncthreads();
        if (tid < NTYPES) atomicAdd(&g_counts[tid], c[tid]);
        return;
    }
    if (bid < HIST_BLOCKS + WCONV_BLOCKS) {
        // ---- W convert: fp32 -> fp16 ----
        int i4 = (bid - HIST_BLOCKS) * 256 + tid;      // [0, 131072)
        float4 v = *(const float4*)(W + (size_t)i4 * 4);
        *(uint2*)(g_Wh + (size_t)i4 * 4) = cvt4(v);
        return;
    }
    // ---- x convert: fp32 -> fp16 (4 float4 per thread) ----
    int base = (bid - HIST_BLOCKS - WCONV_BLOCKS) * 1024 + tid;   // float4 idx
    #pragma unroll
    for (int r = 0; r < 4; ++r) {
        int i4 = base + r * 256;                       // [0, 4194304)
        float4 v = *(const float4*)(x + (size_t)i4 * 4);
        *(uint2*)(g_xh + (size_t)i4 * 4) = cvt4(v);
    }
}

// ============================================================================
// k_scatter: local prefix from g_counts, scatter rows, block 0 writes g_meta,
// last-finishing block resets counters for the next graph replay.
// ============================================================================
__global__ void __launch_bounds__(256) k_scatter(const int* __restrict__ types) {
    __shared__ int c[NTYPES], base[NTYPES];
    __shared__ int padstart[NTYPES], cnt[NTYPES];
    const int tid = threadIdx.x, bid = blockIdx.x;

    if (tid < NTYPES) { c[tid] = 0; cnt[tid] = g_counts[tid]; }
    __syncthreads();
    if (tid == 0) {
        int off = 0;
        for (int t = 0; t < NTYPES; t++) {
            padstart[t] = off;
            off += ((cnt[t] + BM - 1) / BM) * BM;
        }
    }
    __syncthreads();

    int i = bid * 256 + tid;                           // [0, 16384)
    int4 tv = *(const int4*)(types + i * 4);
    int p0 = atomicAdd(&c[tv.x], 1);
    int p1 = atomicAdd(&c[tv.y], 1);
    int p2 = atomicAdd(&c[tv.z], 1);
    int p3 = atomicAdd(&c[tv.w], 1);
    __syncthreads();
    if (tid < NTYPES) base[tid] = atomicAdd(&g_cursor[tid], c[tid]);
    __syncthreads();
    g_idx[padstart[tv.x] + base[tv.x] + p0] = i * 4;
    g_idx[padstart[tv.y] + base[tv.y] + p1] = i * 4 + 1;
    g_idx[padstart[tv.z] + base[tv.z] + p2] = i * 4 + 2;
    g_idx[padstart[tv.w] + base[tv.w] + p3] = i * 4 + 3;

    // block 0: per-tile metadata (type + valid row count in tile)
    if (bid == 0) {
        for (int tile = tid; tile < MAXTILES; tile += 256) {
            int meta = -1;
            for (int t = 0; t < NTYPES; t++) {
                int ts = padstart[t] / BM;
                int tn = (cnt[t] + BM - 1) / BM;
                if (tile >= ts && tile < ts + tn) {
                    int v = cnt[t] - (tile - ts) * BM;
                    if (v > BM) v = BM;
                    meta = t | (v << 8);
                }
            }
            g_meta[tile] = meta;
        }
    }

    // last block to arrive resets the counters for the next graph replay
    __syncthreads();
    __threadfence();
    if (tid == 0) {
        if (atomicAdd(&g_done, 1) == gridDim.x - 1) {
            for (int t = 0; t < NTYPES; t++) { g_counts[t] = 0; g_cursor[t] = 0; }
            g_done = 0;
        }
    }
}

// ============================================================================
// Grouped GEMM: block = (row-tile, N-half). D[128,128] = gather(xh)*Wh^T + b
// Pure cp.async + ldmatrix + mma; 3-stage pipeline, prefetch depth 2.
// 8 warps in 2(M)x4(N); warp tile 64x32; 64 fp32 acc/thread; 2 CTAs/SM.
// (R9 GEMM verbatim; tile type/validity from g_meta.)
// ============================================================================
__global__ void __launch_bounds__(GTHREADS, 2)
typed_linear_gemm(const float* __restrict__ b, float* __restrict__ out) {
    extern __shared__ char smem[];
    const int tile  = blockIdx.x >> 1;
    const int nside = blockIdx.x & 1;
    const int meta = g_meta[tile];
    if (meta < 0) return;
    const int t    = meta & 0xFF;
    const int vcnt = meta >> 8;

    const int tid  = threadIdx.x;
    const int wid  = tid >> 5;
    const int lane = tid & 31;
    const uint32_t sb = smem_u32(smem);

    int*   s_idx  = (int*)smem;
    float* s_bias = (float*)(smem + 512);

    if (tid < BM) s_idx[tid] = (tid < vcnt) ? g_idx[tile * BM + tid] : -1;
    if (tid < BN) s_bias[tid] = b[t * OUT_DIM + nside * BN + tid];
    __syncthreads();

    const __half* Wh_t = g_Wh + ((size_t)t * OUT_DIM + nside * BN) * IN_DIM;

    // Per chunk: A = 128 rows x 64 fp16 gathered (1024 x 16B, 4/thread),
    //            B = 128 rows x 64 fp16           (1024 x 16B, 4/thread).
    auto issue_chunk = [&](int c) {
        const int kb = c * KC;
        const uint32_t stg = sb + OFF_STAGE0 + (uint32_t)(c % 3) * STAGE_BYTES;
        #pragma unroll
        for (int r = 0; r < 4; ++r) {
            int i16 = r * GTHREADS + tid;          // [0,1024)
            int m = i16 >> 3, k16 = i16 & 7;
            int g = s_idx[m];
            uint32_t d = swz((uint32_t)(m * 128 + k16 * 16));
            cpa16(stg + d, g_xh + (size_t)(g < 0 ? 0 : g) * IN_DIM + kb + k16 * 8);
        }
        #pragma unroll
        for (int r = 0; r < 4; ++r) {
            int i16 = r * GTHREADS + tid;          // [0,1024)
            int n = i16 >> 3, k16 = i16 & 7;
            uint32_t d = swz((uint32_t)(n * 128 + k16 * 16));
            cpa16(stg + 16384u + d, Wh_t + (size_t)n * IN_DIM + kb + k16 * 8);
        }
        cpa_commit();
    };

    // -------- warp/lane constants for ldmatrix --------
    const int mgrp = wid >> 2;      // rows [64*mgrp, +64)
    const int nq   = wid & 3;       // cols [32*nq, +32) within the 128-col tile
    const int j = lane & 7, sub = lane >> 3;

    uint32_t a_base[4], a_xr[4], b_base[2], b_xr[2];
    #pragma unroll
    for (int mt = 0; mt < 4; ++mt) {
        int row = mgrp * 64 + mt * 16 + j + (sub & 1) * 8;
        a_xr[mt]   = (uint32_t)((row & 7) * 16);
        a_base[mt] = (uint32_t)(row * 128) + (uint32_t)((sub >> 1) * 16);
    }
    #pragma unroll
    for (int nt = 0; nt < 2; ++nt) {
        int row = nq * 32 + nt * 16 + (sub >> 1) * 8 + j;
        b_xr[nt]   = (uint32_t)((row & 7) * 16);
        b_base[nt] = (uint32_t)(row * 128) + (uint32_t)((sub & 1) * 16);
    }

    float acc[4][4][4];   // [mt][n8][quad]
    #pragma unroll
    for (int mt = 0; mt < 4; ++mt)
        #pragma unroll
        for (int i = 0; i < 4; ++i)
            #pragma unroll
            for (int q = 0; q < 4; ++q) acc[mt][i][q] = 0.f;

    issue_chunk(0);
    issue_chunk(1);

    #pragma unroll
    for (int c = 0; c < NCHUNK; ++c) {
        const uint32_t stg = sb + OFF_STAGE0 + (uint32_t)(c % 3) * STAGE_BYTES;
        const uint32_t Ah = stg, Bh = stg + 16384u;

        if (c == NCHUNK - 1) cpa_wait<0>(); else cpa_wait<1>();   // chunk c arrived
        __syncthreads();   // all warps past compute(c-1); stage (c+2)%3 free

        if (c + 2 < NCHUNK) issue_chunk(c + 2);

        // ---- compute chunk c: 4 K16 steps ----
        #pragma unroll
        for (int ks = 0; ks < 4; ++ks) {
            const uint32_t kb = (uint32_t)(ks * 32);
            uint32_t ah[4][4], bhr[2][4];
            #pragma unroll
            for (int mt = 0; mt < 4; ++mt)
                ldsm4(ah[mt], Ah + ((a_base[mt] + kb) ^ a_xr[mt]));
            #pragma unroll
            for (int nt = 0; nt < 2; ++nt)
                ldsm4(bhr[nt], Bh + ((b_base[nt] + kb) ^ b_xr[nt]));
            #pragma unroll
            for (int nt = 0; nt < 2; ++nt)
                #pragma unroll
                for (int mt = 0; mt < 4; ++mt) {
                    mma16816(acc[mt][2 * nt],     ah[mt], bhr[nt][0], bhr[nt][1]);
                    mma16816(acc[mt][2 * nt + 1], ah[mt], bhr[nt][2], bhr[nt][3]);
                }
        }
    }

    // ---- epilogue: bias + scatter-store (streaming) ----
    #pragma unroll
    for (int mt = 0; mt < 4; ++mt) {
        const int r0 = mgrp * 64 + mt * 16 + (lane >> 2);
        const int g0 = s_idx[r0];
        const int g1 = s_idx[r0 + 8];
        #pragma unroll
        for (int n8 = 0; n8 < 4; ++n8) {
            const int lcol = nq * 32 + n8 * 8 + (lane & 3) * 2;
            const int col  = nside * BN + lcol;
            const float bv0 = s_bias[lcol], bv1 = s_bias[lcol + 1];
            if (g0 >= 0)
                stcs2(out + (size_t)g0 * OUT_DIM + col,
                      make_float2(acc[mt][n8][0] + bv0, acc[mt][n8][1] + bv1));
            if (g1 >= 0)
                stcs2(out + (size_t)g1 * OUT_DIM + col,
                      make_float2(acc[mt][n8][2] + bv0, acc[mt][n8][3] + bv1));
        }
    }
}

// ============================================================================
// Launch
// ============================================================================
extern "C" void kernel_launch(void* const* d_in, const int* in_sizes, int n_in,
                              void* d_out, int out_size) {
    const float* x     = (const float*)d_in[0];
    const int*   types = (const int*)d_in[1];
    const float* W     = (const float*)d_in[2];
    const float* b     = (const float*)d_in[3];
    float*       out   = (float*)d_out;

    cudaFuncSetAttribute(typed_linear_gemm, cudaFuncAttributeMaxDynamicSharedMemorySize,
                         SMEM_BYTES);

    k_prep1<<<HIST_BLOCKS + WCONV_BLOCKS + XCONV_BLOCKS, 256>>>(W, x, types);
    k_scatter<<<HIST_BLOCKS, 256>>>(types);
    typed_linear_gemm<<<MAXTILES * 2, GTHREADS, SMEM_BYTES>>>(b, out);
}

// round 14
// speedup vs baseline: 1.1616x; 1.0396x over previous
#include <cuda_runtime.h>
#include <cuda_fp16.h>
#include <cstdint>

// ============================================================================
// Problem constants
// ============================================================================
#define N_ROWS   65536
#define IN_DIM   256
#define OUT_DIM  256
#define NTYPES   8
#define BM       128                       // rows per block tile
#define BN       128                       // cols per block tile (OUT split in 2)
#define MAXTILES (N_ROWS / BM + NTYPES)    // 520 row-tiles
#define KC       64                        // K-chunk
#define NCHUNK   (IN_DIM / KC)             // 4
#define GTHREADS 256
#define SCAT_BLOCKS 64
#define WCONV_BLOCKS 512
#define XCONV_BLOCKS 4096

// SMEM layout (bytes) for GEMM:
//  [0]      s_idx[128]     512B
//  [512]    s_bias[128]    512B
//  [1024]   3 stages x (Ah 16K | Bh 16K) = 96K
#define OFF_STAGE0  1024
#define STAGE_BYTES 32768
#define SMEM_BYTES  99328

// ============================================================================
// Device scratch
// ============================================================================
__device__ int g_cursor[NTYPES];   // reset by last scatter block each replay
__device__ int g_done;             // scatter completion counter (self-resetting)
__device__ int g_idx[MAXTILES * BM];
__device__ int g_meta[MAXTILES];   // per tile: type | (valid_count << 8), or -1
__device__ __align__(16) __half g_Wh[NTYPES * OUT_DIM * IN_DIM];
__device__ __align__(16) __half g_xh[N_ROWS * IN_DIM];          // 32 MB fp16 x

// ============================================================================
// Helpers
// ============================================================================
__device__ __forceinline__ uint32_t smem_u32(const void* p) {
    uint32_t a;
    asm("{ .reg .u64 t; cvta.to.shared.u64 t, %1; cvt.u32.u64 %0, t; }" : "=r"(a) : "l"(p));
    return a;
}

__device__ __forceinline__ uint32_t swz(uint32_t off) { return off ^ ((off >> 3) & 0x70); }

__device__ __forceinline__ void cpa16(uint32_t dst, const void* src) {
    asm volatile("cp.async.cg.shared.global [%0], [%1], 16;" :: "r"(dst), "l"(src));
}
__device__ __forceinline__ void cpa_commit() {
    asm volatile("cp.async.commit_group;");
}
template <int N> __device__ __forceinline__ void cpa_wait() {
    asm volatile("cp.async.wait_group %0;" :: "n"(N) : "memory");
}

__device__ __forceinline__ void ldsm4(uint32_t* r, uint32_t addr) {
    asm volatile("ldmatrix.sync.aligned.m8n8.x4.shared.b16 {%0,%1,%2,%3}, [%4];"
                 : "=r"(r[0]), "=r"(r[1]), "=r"(r[2]), "=r"(r[3]) : "r"(addr));
}

__device__ __forceinline__ void mma16816(float* c, const uint32_t* a, uint32_t b0, uint32_t b1) {
    asm volatile("mma.sync.aligned.m16n8k16.row.col.f32.f16.f16.f32 "
                 "{%0,%1,%2,%3}, {%4,%5,%6,%7}, {%8,%9}, {%0,%1,%2,%3};"
                 : "+f"(c[0]), "+f"(c[1]), "+f"(c[2]), "+f"(c[3])
                 : "r"(a[0]), "r"(a[1]), "r"(a[2]), "r"(a[3]), "r"(b0), "r"(b1));
}

__device__ __forceinline__ uint32_t h2_as_u32(__half2 h) {
    return *reinterpret_cast<uint32_t*>(&h);
}

__device__ __forceinline__ void stcs2(float* p, float2 v) {
    asm volatile("st.global.cs.v2.f32 [%0], {%1, %2};" :: "l"(p), "f"(v.x), "f"(v.y));
}

__device__ __forceinline__ uint2 cvt4(float4 v) {
    __half2 h01 = __floats2half2_rn(v.x, v.y);
    __half2 h23 = __floats2half2_rn(v.z, v.w);
    return make_uint2(h2_as_u32(h01), h2_as_u32(h23));
}

// evict-first fp32x4 load (stream-once data; keep L2 for g_xh/g_Wh)
__device__ __forceinline__ float4 ldcs4(const float* p) {
    float4 v;
    asm volatile("ld.global.cs.v4.f32 {%0,%1,%2,%3}, [%4];"
                 : "=f"(v.x), "=f"(v.y), "=f"(v.z), "=f"(v.w) : "l"(p));
    return v;
}

// ============================================================================
// k_prep: ONE kernel.
//   blocks [0,64): scatter (each block builds the FULL type histogram locally
//                  -> identical padstart everywhere, no cross-kernel dep)
//   blocks [64,576): W fp32->fp16
//   blocks [576,4672): x fp32->fp16
// ============================================================================
__global__ void __launch_bounds__(256) k_prep(const float* __restrict__ W,
                                              const float* __restrict__ x,
                                              const int* __restrict__ types) {
    const int bid = blockIdx.x, tid = threadIdx.x;

    if (bid < SCAT_BLOCKS) {
        __shared__ int h[NTYPES];                       // global histogram
        __shared__ int c[NTYPES], base[NTYPES], padstart[NTYPES];
        if (tid < NTYPES) { h[tid] = 0; c[tid] = 0; }
        __syncthreads();

        // ---- full histogram, packed 8-bit lanes, 2 batches of 128 vals ----
        const int4* t4 = (const int4*)types;            // 16384 int4 total
        #pragma unroll
        for (int batch = 0; batch < 2; ++batch) {
            unsigned long long pk = 0;
            #pragma unroll
            for (int r = 0; r < 32; ++r) {
                int4 tv = t4[(batch * 32 + r) * 256 + tid];
                pk += (1ULL << (8 * tv.x)) + (1ULL << (8 * tv.y))
                    + (1ULL << (8 * tv.z)) + (1ULL << (8 * tv.w));
            }
            #pragma unroll
            for (int t = 0; t < NTYPES; ++t)
                atomicAdd(&h[t], (int)((pk >> (8 * t)) & 0xFF));
        }
        __syncthreads();
        if (tid == 0) {
            int off = 0;
            for (int t = 0; t < NTYPES; t++) {
                padstart[t] = off;
                off += ((h[t] + BM - 1) / BM) * BM;
            }
        }
        __syncthreads();

        // ---- scatter this block's 1024 elements ----
        int i = bid * 256 + tid;                        // [0, 16384)
        int4 tv = t4[i];
        int p0 = atomicAdd(&c[tv.x], 1);
        int p1 = atomicAdd(&c[tv.y], 1);
        int p2 = atomicAdd(&c[tv.z], 1);
        int p3 = atomicAdd(&c[tv.w], 1);
        __syncthreads();
        if (tid < NTYPES) base[tid] = atomicAdd(&g_cursor[tid], c[tid]);
        __syncthreads();
        g_idx[padstart[tv.x] + base[tv.x] + p0] = i * 4;
        g_idx[padstart[tv.y] + base[tv.y] + p1] = i * 4 + 1;
        g_idx[padstart[tv.z] + base[tv.z] + p2] = i * 4 + 2;
        g_idx[padstart[tv.w] + base[tv.w] + p3] = i * 4 + 3;

        // ---- block 0: per-tile metadata ----
        if (bid == 0) {
            for (int tile = tid; tile < MAXTILES; tile += 256) {
                int meta = -1;
                for (int t = 0; t < NTYPES; t++) {
                    int ts = padstart[t] / BM;
                    int tn = (h[t] + BM - 1) / BM;
                    if (tile >= ts && tile < ts + tn) {
                        int v = h[t] - (tile - ts) * BM;
                        if (v > BM) v = BM;
                        meta = t | (v << 8);
                    }
                }
                g_meta[tile] = meta;
            }
        }

        // ---- last scatter block resets cursor for the next graph replay ----
        __syncthreads();
        __threadfence();
        if (tid == 0) {
            if (atomicAdd(&g_done, 1) == SCAT_BLOCKS - 1) {
                for (int t = 0; t < NTYPES; t++) g_cursor[t] = 0;
                g_done = 0;
            }
        }
        return;
    }

    if (bid < SCAT_BLOCKS + WCONV_BLOCKS) {
        // ---- W convert: fp32 -> fp16 (evict-first reads) ----
        int i4 = (bid - SCAT_BLOCKS) * 256 + tid;       // [0, 131072)
        float4 v = ldcs4(W + (size_t)i4 * 4);
        *(uint2*)(g_Wh + (size_t)i4 * 4) = cvt4(v);
        return;
    }
    // ---- x convert: fp32 -> fp16 (4 float4 per thread, evict-first reads) ----
    int base4 = (bid - SCAT_BLOCKS - WCONV_BLOCKS) * 1024 + tid;  // float4 idx
    #pragma unroll
    for (int r = 0; r < 4; ++r) {
        int i4 = base4 + r * 256;                       // [0, 4194304)
        float4 v = ldcs4(x + (size_t)i4 * 4);
        *(uint2*)(g_xh + (size_t)i4 * 4) = cvt4(v);
    }
}

// ============================================================================
// Grouped GEMM: block = (row-tile, N-half). D[128,128] = gather(xh)*Wh^T + b
// Pure cp.async + ldmatrix + mma; 3-stage pipeline, prefetch depth 2.
// 8 warps in 2(M)x4(N); warp tile 64x32; 64 fp32 acc/thread; 2 CTAs/SM.
// ============================================================================
__global__ void __launch_bounds__(GTHREADS, 2)
typed_linear_gemm(const float* __restrict__ b, float* __restrict__ out) {
    extern __shared__ char smem[];
    const int tile  = blockIdx.x >> 1;
    const int nside = blockIdx.x & 1;
    const int meta = g_meta[tile];
    if (meta < 0) return;
    const int t    = meta & 0xFF;
    const int vcnt = meta >> 8;

    const int tid  = threadIdx.x;
    const int wid  = tid >> 5;
    const int lane = tid & 31;
    const uint32_t sb = smem_u32(smem);

    int*   s_idx  = (int*)smem;
    float* s_bias = (float*)(smem + 512);

    if (tid < BM) s_idx[tid] = (tid < vcnt) ? g_idx[tile * BM + tid] : -1;
    if (tid < BN) s_bias[tid] = b[t * OUT_DIM + nside * BN + tid];
    __syncthreads();

    const __half* Wh_t = g_Wh + ((size_t)t * OUT_DIM + nside * BN) * IN_DIM;

    // Per chunk: A = 128 rows x 64 fp16 gathered (1024 x 16B, 4/thread),
    //            B = 128 rows x 64 fp16           (1024 x 16B, 4/thread).
    auto issue_chunk = [&](int c) {
        const int kb = c * KC;
        const uint32_t stg = sb + OFF_STAGE0 + (uint32_t)(c % 3) * STAGE_BYTES;
        #pragma unroll
        for (int r = 0; r < 4; ++r) {
            int i16 = r * GTHREADS + tid;          // [0,1024)
            int m = i16 >> 3, k16 = i16 & 7;
            int g = s_idx[m];
            uint32_t d = swz((uint32_t)(m * 128 + k16 * 16));
            cpa16(stg + d, g_xh + (size_t)(g < 0 ? 0 : g) * IN_DIM + kb + k16 * 8);
        }
        #pragma unroll
        for (int r = 0; r < 4; ++r) {
            int i16 = r * GTHREADS + tid;          // [0,1024)
            int n = i16 >> 3, k16 = i16 & 7;
            uint32_t d = swz((uint32_t)(n * 128 + k16 * 16));
            cpa16(stg + 16384u + d, Wh_t + (size_t)n * IN_DIM + kb + k16 * 8);
        }
        cpa_commit();
    };

    // -------- warp/lane constants for ldmatrix --------
    const int mgrp = wid >> 2;      // rows [64*mgrp, +64)
    const int nq   = wid & 3;       // cols [32*nq, +32) within the 128-col tile
    const int j = lane & 7, sub = lane >> 3;

    uint32_t a_base[4], a_xr[4], b_base[2], b_xr[2];
    #pragma unroll
    for (int mt = 0; mt < 4; ++mt) {
        int row = mgrp * 64 + mt * 16 + j + (sub & 1) * 8;
        a_xr[mt]   = (uint32_t)((row & 7) * 16);
        a_base[mt] = (uint32_t)(row * 128) + (uint32_t)((sub >> 1) * 16);
    }
    #pragma unroll
    for (int nt = 0; nt < 2; ++nt) {
        int row = nq * 32 + nt * 16 + (sub >> 1) * 8 + j;
        b_xr[nt]   = (uint32_t)((row & 7) * 16);
        b_base[nt] = (uint32_t)(row * 128) + (uint32_t)((sub & 1) * 16);
    }

    float acc[4][4][4];   // [mt][n8][quad]
    #pragma unroll
    for (int mt = 0; mt < 4; ++mt)
        #pragma unroll
        for (int i = 0; i < 4; ++i)
            #pragma unroll
            for (int q = 0; q < 4; ++q) acc[mt][i][q] = 0.f;

    issue_chunk(0);
    issue_chunk(1);

    #pragma unroll
    for (int c = 0; c < NCHUNK; ++c) {
        const uint32_t stg = sb + OFF_STAGE0 + (uint32_t)(c % 3) * STAGE_BYTES;
        const uint32_t Ah = stg, Bh = stg + 16384u;

        if (c == NCHUNK - 1) cpa_wait<0>(); else cpa_wait<1>();   // chunk c arrived
        __syncthreads();   // all warps past compute(c-1); stage (c+2)%3 free

        if (c + 2 < NCHUNK) issue_chunk(c + 2);

        // ---- compute chunk c: 4 K16 steps ----
        #pragma unroll
        for (int ks = 0; ks < 4; ++ks) {
            const uint32_t kb = (uint32_t)(ks * 32);
            uint32_t ah[4][4], bhr[2][4];
            #pragma unroll
            for (int mt = 0; mt < 4; ++mt)
                ldsm4(ah[mt], Ah + ((a_base[mt] + kb) ^ a_xr[mt]));
            #pragma unroll
            for (int nt = 0; nt < 2; ++nt)
                ldsm4(bhr[nt], Bh + ((b_base[nt] + kb) ^ b_xr[nt]));
            #pragma unroll
            for (int nt = 0; nt < 2; ++nt)
                #pragma unroll
                for (int mt = 0; mt < 4; ++mt) {
                    mma16816(acc[mt][2 * nt],     ah[mt], bhr[nt][0], bhr[nt][1]);
                    mma16816(acc[mt][2 * nt + 1], ah[mt], bhr[nt][2], bhr[nt][3]);
                }
        }
    }

    // ---- epilogue: bias + scatter-store (streaming) ----
    #pragma unroll
    for (int mt = 0; mt < 4; ++mt) {
        const int r0 = mgrp * 64 + mt * 16 + (lane >> 2);
        const int g0 = s_idx[r0];
        const int g1 = s_idx[r0 + 8];
        #pragma unroll
        for (int n8 = 0; n8 < 4; ++n8) {
            const int lcol = nq * 32 + n8 * 8 + (lane & 3) * 2;
            const int col  = nside * BN + lcol;
            const float bv0 = s_bias[lcol], bv1 = s_bias[lcol + 1];
            if (g0 >= 0)
                stcs2(out + (size_t)g0 * OUT_DIM + col,
                      make_float2(acc[mt][n8][0] + bv0, acc[mt][n8][1] + bv1));
            if (g1 >= 0)
                stcs2(out + (size_t)g1 * OUT_DIM + col,
                      make_float2(acc[mt][n8][2] + bv0, acc[mt][n8][3] + bv1));
        }
    }
}

// ============================================================================
// Launch (2 kernels total)
// ============================================================================
extern "C" void kernel_launch(void* const* d_in, const int* in_sizes, int n_in,
                              void* d_out, int out_size) {
    const float* x     = (const float*)d_in[0];
    const int*   types = (const int*)d_in[1];
    const float* W     = (const float*)d_in[2];
    const float* b     = (const float*)d_in[3];
    float*       out   = (float*)d_out;

    cudaFuncSetAttribute(typed_linear_gemm, cudaFuncAttributeMaxDynamicSharedMemorySize,
                         SMEM_BYTES);

    k_prep<<<SCAT_BLOCKS + WCONV_BLOCKS + XCONV_BLOCKS, 256>>>(W, x, types);
    typed_linear_gemm<<<MAXTILES * 2, GTHREADS, SMEM_BYTES>>>(b, out);
}